// round 16
// baseline (speedup 1.0000x reference)
#include <cuda_runtime.h>
#include <cuda_fp16.h>
#include <cstdint>

#define SS 4096
#define DD 1024
#define HH 16
#define DHH 64
#define SCALE_L2E 0.045111762f             // (1/32) * log2(e)

// pack two f32 -> half2 (lo = first arg)
__device__ __forceinline__ uint32_t pkh2(float lo, float hi) {
    uint32_t r;
    asm("cvt.rn.f16x2.f32 %0, %1, %2;" : "=r"(r) : "f"(hi), "f"(lo));
    return r;
}
__device__ __forceinline__ uint32_t h2exp2(uint32_t x) {
    uint32_t r; asm("ex2.approx.f16x2 %0, %1;" : "=r"(r) : "r"(x)); return r;
}
__device__ __forceinline__ void mma_f16(float* d, const uint32_t* a,
                                        uint32_t b0, uint32_t b1) {
    asm volatile(
        "mma.sync.aligned.m16n8k16.row.col.f32.f16.f16.f32 "
        "{%0,%1,%2,%3}, {%4,%5,%6,%7}, {%8,%9}, {%0,%1,%2,%3};"
        : "+f"(d[0]), "+f"(d[1]), "+f"(d[2]), "+f"(d[3])
        : "r"(a[0]), "r"(a[1]), "r"(a[2]), "r"(a[3]), "r"(b0), "r"(b1));
}
// f16 accumulator variant (C/D = 2 regs of half2)
__device__ __forceinline__ void mma_f16c16(uint32_t* d, const uint32_t* a,
                                           uint32_t b0, uint32_t b1) {
    asm volatile(
        "mma.sync.aligned.m16n8k16.row.col.f16.f16.f16.f16 "
        "{%0,%1}, {%2,%3,%4,%5}, {%6,%7}, {%0,%1};"
        : "+r"(d[0]), "+r"(d[1])
        : "r"(a[0]), "r"(a[1]), "r"(a[2]), "r"(a[3]), "r"(b0), "r"(b1));
}
__device__ __forceinline__ uint32_t smem_to_u32(const void* p) {
    uint32_t a;
    asm("{ .reg .u64 t; cvta.to.shared.u64 t, %1; cvt.u32.u64 %0, t; }"
        : "=r"(a) : "l"(p));
    return a;
}
__device__ __forceinline__ void cp16(uint32_t dst, const void* src) {
    size_t g = __cvta_generic_to_global(src);
    asm volatile("cp.async.cg.shared.global [%0], [%1], 16;"
                 :: "r"(dst), "l"(g) : "memory");
}
#define CP_COMMIT() asm volatile("cp.async.commit_group;" ::: "memory")
#define CP_WAIT0()  asm volatile("cp.async.wait_group 0;" ::: "memory")

// Scratch (all fp16, stored as packed uint32 words = half2)
__device__ uint32_t g_X[3 * SS * DD / 2];     // q,k,v inputs [z][s][d]
__device__ uint32_t g_Q[HH * SS * DHH / 2];   // [h][s][e], pre-scaled by SCALE_L2E
__device__ uint32_t g_K[HH * SS * DHH / 2];   // [h][s][e]
__device__ uint32_t g_V[HH * SS * DHH / 2];   // [h][s/2][e][2] key-pair interleaved
__device__ uint32_t g_O[HH * SS * DHH / 2];   // [h][s][e]
__device__ uint32_t g_WT[64 * 64 * 1024 / 2]; // [slab][n][k] transposed weights

// ---------------------------------------------------------------------------
// Pre-convert q,k,v to fp16
// ---------------------------------------------------------------------------
__global__ __launch_bounds__(256) void preconv(
    const float* __restrict__ q, const float* __restrict__ k,
    const float* __restrict__ v)
{
    const int n4 = SS * DD / 4;
    for (int idx = blockIdx.x * 256 + threadIdx.x; idx < 3 * n4;
         idx += gridDim.x * 256) {
        int which = idx / n4, off = idx - which * n4;
        const float* src = (which == 0) ? q : (which == 1) ? k : v;
        float4 vv = *(const float4*)(src + (size_t)off * 4);
        uint2 u;
        u.x = pkh2(vv.x, vv.y);
        u.y = pkh2(vv.z, vv.w);
        *(uint2*)(g_X + (size_t)idx * 2) = u;
    }
}

// ---------------------------------------------------------------------------
// Weight pre-transpose: W[d][e] -> g_WT[slab][e][d] fp16
// ---------------------------------------------------------------------------
__global__ __launch_bounds__(256) void transpose_w(
    const float* __restrict__ Wq, const float* __restrict__ Wk,
    const float* __restrict__ Wv, const float* __restrict__ Wo)
{
    __shared__ float tile[32][33];
    const int slab = blockIdx.z, which = slab >> 4, hh = slab & 15;
    const float* src; int ld; size_t off;
    if (which == 0)      { src = Wq; ld = DHH; off = (size_t)hh * DD * DHH; }
    else if (which == 1) { src = Wk; ld = DHH; off = (size_t)hh * DD * DHH; }
    else if (which == 2) { src = Wv; ld = DHH; off = (size_t)hh * DD * DHH; }
    else                 { src = Wo; ld = DD;  off = (size_t)hh * 64; }
    const int d0 = blockIdx.x * 32, e0 = blockIdx.y * 32;
    const int tx = threadIdx.x, ty = threadIdx.y;
    #pragma unroll
    for (int j = 0; j < 32; j += 8)
        tile[ty + j][tx] = src[off + (size_t)(d0 + ty + j) * ld + e0 + tx];
    __syncthreads();
    __half* dst = (__half*)g_WT + (size_t)slab * 65536;
    #pragma unroll
    for (int j = 0; j < 32; j += 8)
        dst[(size_t)(e0 + ty + j) * 1024 + d0 + tx] =
            __float2half_rn(tile[tx][ty + j]);
}

// ---------------------------------------------------------------------------
// QKV projection, fp16 m16n8k16. CTA = (128 s-rows, head, which).
// ---------------------------------------------------------------------------
#define PROJ_SMEM ((128 * 36 + 64 * 36) * 4)

__global__ __launch_bounds__(256, 2) void proj_mma_kernel(
    const float* __restrict__ bq, const float* __restrict__ bk,
    const float* __restrict__ bv)
{
    extern __shared__ uint32_t sm[];
    uint32_t* As = sm;            // [128][36]
    uint32_t* Ws = sm + 128 * 36; // [64][36]

    const int z  = blockIdx.z;
    const int h  = blockIdx.y;
    const int m0 = blockIdx.x * 128;
    const uint32_t* A  = g_X + (size_t)z * SS * DD / 2;
    const float* biasp = ((z == 0) ? bq : (z == 1) ? bk : bv) + h * DHH;
    uint32_t* out = ((z == 0) ? g_Q : (z == 1) ? g_K : g_V)
                    + (size_t)h * SS * DHH / 2;
    const uint32_t* WT = g_WT + (size_t)(z * 16 + h) * 32768;

    const int t = threadIdx.x, wid = t >> 5, lane = t & 31;
    const int m0w = (wid >> 1) * 32, n0w = (wid & 1) * 32;
    const int lq = lane >> 2, ll = lane & 3;

    float c[2][4][4] = {};

    for (int kc = 0; kc < 16; kc++) {
        __syncthreads();
        #pragma unroll
        for (int it = 0; it < 4; it++) {
            int idx = t + it * 256;
            int r = idx >> 3, cc = (idx & 7) * 4;
            *(uint4*)(As + r * 36 + cc) =
                *(const uint4*)(A + (size_t)(m0 + r) * 512 + kc * 32 + cc);
        }
        #pragma unroll
        for (int it = 0; it < 2; it++) {
            int idx = t + it * 256;
            int e = idx >> 3, cc = (idx & 7) * 4;
            *(uint4*)(Ws + e * 36 + cc) =
                *(const uint4*)(WT + (size_t)e * 512 + kc * 32 + cc);
        }
        __syncthreads();

        #pragma unroll
        for (int ks = 0; ks < 4; ks++) {
            const int kb = ks * 8 + ll;
            uint32_t a[2][4];
            #pragma unroll
            for (int mt = 0; mt < 2; mt++) {
                int row = m0w + mt * 16 + lq;
                a[mt][0] = As[row * 36 + kb];
                a[mt][1] = As[(row + 8) * 36 + kb];
                a[mt][2] = As[row * 36 + kb + 4];
                a[mt][3] = As[(row + 8) * 36 + kb + 4];
            }
            #pragma unroll
            for (int nt = 0; nt < 4; nt++) {
                int n = n0w + nt * 8 + lq;
                uint32_t b0 = Ws[n * 36 + kb];
                uint32_t b1 = Ws[n * 36 + kb + 4];
                mma_f16(c[0][nt], a[0], b0, b1);
                mma_f16(c[1][nt], a[1], b0, b1);
            }
        }
    }

    if (z == 2) {
        __half* oh = (__half*)out;
        #pragma unroll
        for (int mt = 0; mt < 2; mt++) {
            #pragma unroll
            for (int nt = 0; nt < 4; nt++) {
                int col = n0w + nt * 8 + 2 * ll;
                float b0 = biasp[col], b1 = biasp[col + 1];
                #pragma unroll
                for (int rr = 0; rr < 2; rr++) {
                    int s = m0 + m0w + mt * 16 + lq + rr * 8;
                    size_t base = (size_t)(s >> 1) * 128 + (s & 1);
                    oh[base + col * 2] =
                        __float2half_rn(c[mt][nt][rr * 2 + 0] + b0);
                    oh[base + (col + 1) * 2] =
                        __float2half_rn(c[mt][nt][rr * 2 + 1] + b1);
                }
            }
        }
    } else {
        const float osc = (z == 0) ? SCALE_L2E : 1.0f;
        #pragma unroll
        for (int mt = 0; mt < 2; mt++) {
            #pragma unroll
            for (int nt = 0; nt < 4; nt++) {
                int col = n0w + nt * 8 + 2 * ll;
                float b0 = biasp[col], b1 = biasp[col + 1];
                #pragma unroll
                for (int rr = 0; rr < 2; rr++) {
                    int s = m0 + m0w + mt * 16 + lq + rr * 8;
                    out[(size_t)s * 32 + (col >> 1)] =
                        pkh2((c[mt][nt][rr * 2 + 0] + b0) * osc,
                             (c[mt][nt][rr * 2 + 1] + b1) * osc);
                }
            }
        }
    }
}

// ---------------------------------------------------------------------------
// Output projection, fp16. Chunk kc == head (gather from g_O). f32 output.
// ---------------------------------------------------------------------------
__global__ __launch_bounds__(256, 2) void outproj_mma_kernel(
    const float* __restrict__ bo, float* __restrict__ Cout)
{
    extern __shared__ uint32_t sm[];
    uint32_t* As = sm;
    uint32_t* Ws = sm + 128 * 36;

    const int m0 = blockIdx.x * 128;
    const int n0 = blockIdx.y * 64;
    const uint32_t* WT = g_WT + (size_t)(48 + blockIdx.y) * 32768;
    const float* biasp = bo + n0;

    const int t = threadIdx.x, wid = t >> 5, lane = t & 31;
    const int m0w = (wid >> 1) * 32, n0w = (wid & 1) * 32;
    const int lq = lane >> 2, ll = lane & 3;

    float c[2][4][4] = {};

    for (int kc = 0; kc < 16; kc++) {
        const uint32_t* A = g_O + (size_t)kc * SS * 32;
        __syncthreads();
        #pragma unroll
        for (int it = 0; it < 4; it++) {
            int idx = t + it * 256;
            int r = idx >> 3, cc = (idx & 7) * 4;
            *(uint4*)(As + r * 36 + cc) =
                *(const uint4*)(A + (size_t)(m0 + r) * 32 + cc);
        }
        #pragma unroll
        for (int it = 0; it < 2; it++) {
            int idx = t + it * 256;
            int e = idx >> 3, cc = (idx & 7) * 4;
            *(uint4*)(Ws + e * 36 + cc) =
                *(const uint4*)(WT + (size_t)e * 512 + kc * 32 + cc);
        }
        __syncthreads();

        #pragma unroll
        for (int ks = 0; ks < 4; ks++) {
            const int kb = ks * 8 + ll;
            uint32_t a[2][4];
            #pragma unroll
            for (int mt = 0; mt < 2; mt++) {
                int row = m0w + mt * 16 + lq;
                a[mt][0] = As[row * 36 + kb];
                a[mt][1] = As[(row + 8) * 36 + kb];
                a[mt][2] = As[row * 36 + kb + 4];
                a[mt][3] = As[(row + 8) * 36 + kb + 4];
            }
            #pragma unroll
            for (int nt = 0; nt < 4; nt++) {
                int n = n0w + nt * 8 + lq;
                uint32_t b0 = Ws[n * 36 + kb];
                uint32_t b1 = Ws[n * 36 + kb + 4];
                mma_f16(c[0][nt], a[0], b0, b1);
                mma_f16(c[1][nt], a[1], b0, b1);
            }
        }
    }

    #pragma unroll
    for (int mt = 0; mt < 2; mt++) {
        int row = m0w + mt * 16 + lq;
        #pragma unroll
        for (int nt = 0; nt < 4; nt++) {
            int col = n0w + nt * 8 + 2 * ll;
            float2 o0 = make_float2(c[mt][nt][0] + biasp[col],
                                    c[mt][nt][1] + biasp[col + 1]);
            float2 o1 = make_float2(c[mt][nt][2] + biasp[col],
                                    c[mt][nt][3] + biasp[col + 1]);
            *(float2*)(Cout + (size_t)(m0 + row) * DD + n0 + col) = o0;
            *(float2*)(Cout + (size_t)(m0 + row + 8) * DD + n0 + col) = o1;
        }
    }
}

// ---------------------------------------------------------------------------
// Flash attention, fp16 m16n8k16. CTA = 128 q-rows, 512 threads, 16 warps
// as 8m x 2n: warp = 16 q-rows x 64 keys (one m16 tile — no mt loop).
// f16 S-accum (sC16[8][2]), in-place exp, zero-pack PV A-frags, ones-column
// row sums. ~110 regs -> no spill at 128 cap -> 4 warps/SMSP.
// 128-key chunks, cp.async double-buffered.
// smem (words): Qs[128*36=4608] | Ks0[128*36] | Ks1 | Vs0[64*72=4608] | Vs1
//   = 23040 words (90 KB), 1 CTA/SM.
// Epilogue reuse: Opart @0 ([128][68] f32), lred @8704 ([2][128]).
// ---------------------------------------------------------------------------
#define ATTN_SMEM (23040 * 4)

__global__ __launch_bounds__(512, 1) void attn_kernel()
{
    extern __shared__ uint32_t smu[];
    const uint32_t sb = smem_to_u32(smu);
    uint32_t* Qs = smu;                              // [128][36]
    uint32_t* Ksb[2] = { smu + 4608, smu + 9216 };   // each [128][36]
    uint32_t* Vsb[2] = { smu + 13824, smu + 18432 }; // each [64][72]
    const uint32_t ksw[2] = { sb + 4608 * 4, sb + 9216 * 4 };
    const uint32_t vsw[2] = { sb + 13824 * 4, sb + 18432 * 4 };
    float* Opart = (float*)smu;            // [128][68]
    float* lred  = (float*)(smu + 8704);   // [2][128]

    const int t      = threadIdx.x;
    const int wid    = t >> 5;
    const int lane   = t & 31;
    const int warp_n = wid & 1;
    const int m0w    = (wid >> 1) * 16;    // 8 m-warps x 16 rows
    const int n0w    = warp_n * 64;
    const int lq     = lane >> 2;
    const int ll     = lane & 3;
    const uint32_t oneb = (lq == 0) ? 0x3C003C00u : 0u;  // ones-column B frag

    const int m0 = blockIdx.x * 128;
    const int h  = blockIdx.y;
    const uint32_t* Qg = g_Q + (size_t)h * SS * 32;
    const uint32_t* Kg = g_K + (size_t)h * SS * 32;
    const uint32_t* Vg = g_V + (size_t)h * SS * 32;

    // Load one 128-key chunk (K: 128 rows x 128B, V: 64 kp rows x 256B)
    auto issue_kv = [&](int kb0, int buf) {
        #pragma unroll
        for (int it = 0; it < 2; it++) {
            int idx = t + it * 512;
            int r = idx >> 3, cc = (idx & 7) * 4;
            cp16(ksw[buf] + (r * 36 + cc) * 4,
                 Kg + (size_t)(kb0 + r) * 32 + cc);
        }
        #pragma unroll
        for (int it = 0; it < 2; it++) {
            int idx = t + it * 512;
            int r = idx >> 4, cc = (idx & 15) * 4;
            cp16(vsw[buf] + (r * 72 + cc) * 4,
                 Vg + (size_t)((kb0 >> 1) + r) * 64 + cc);
        }
        CP_COMMIT();
    };

    // Q fill: 128 rows x 128B
    #pragma unroll
    for (int it = 0; it < 2; it++) {
        int idx = t + it * 512;
        int r = idx >> 3, cc = (idx & 7) * 4;
        cp16(sb + (r * 36 + cc) * 4, Qg + (size_t)(m0 + r) * 32 + cc);
    }
    issue_kv(0, 0);

    float oC[8][4];
    #pragma unroll
    for (int nt = 0; nt < 8; nt++)
        #pragma unroll
        for (int i = 0; i < 4; i++) oC[nt][i] = 0.0f;
    float lC[4] = {};

    for (int kt = 0; kt < 32; kt++) {
        const int cur = kt & 1;
        CP_WAIT0();
        __syncthreads();
        if (kt < 31) issue_kv((kt + 1) * 128, cur ^ 1);

        uint32_t* Ks = Ksb[cur];
        uint32_t* Vs = Vsb[cur];

        // S = Q K^T over this warp's 64 keys, f16 accum: sC16[8][2]
        uint32_t sC16[8][2];
        #pragma unroll
        for (int nt = 0; nt < 8; nt++) {
            sC16[nt][0] = 0u; sC16[nt][1] = 0u;
        }
        #pragma unroll
        for (int ks = 0; ks < 4; ks++) {
            const int kb = ks * 8 + ll;
            uint32_t a[4];
            a[0] = Qs[(m0w + lq) * 36 + kb];
            a[1] = Qs[(m0w + 8 + lq) * 36 + kb];
            a[2] = Qs[(m0w + lq) * 36 + kb + 4];
            a[3] = Qs[(m0w + 8 + lq) * 36 + kb + 4];
            #pragma unroll
            for (int nt = 0; nt < 8; nt++) {
                int key = n0w + nt * 8 + lq;
                uint32_t b0 = Ks[key * 36 + kb];
                uint32_t b1 = Ks[key * 36 + kb + 4];
                mma_f16c16(sC16[nt], a, b0, b1);
            }
        }

        // P = 2^S in place (scale folded into Q)
        #pragma unroll
        for (int nt = 0; nt < 8; nt++) {
            sC16[nt][0] = h2exp2(sC16[nt][0]);
            sC16[nt][1] = h2exp2(sC16[nt][1]);
        }

        // O += P V over 64 keys (4 k16 steps); l += P * ones
        #pragma unroll
        for (int ks = 0; ks < 4; ks++) {
            int vbase = (n0w >> 1) + ks * 8;
            mma_f16(lC, &sC16[2 * ks][0], oneb, oneb);
            #pragma unroll
            for (int nt2 = 0; nt2 < 8; nt2++) {
                int e = nt2 * 8 + lq;
                uint32_t b0 = Vs[(vbase + ll) * 72 + e];
                uint32_t b1 = Vs[(vbase + ll + 4) * 72 + e];
                mma_f16(oC[nt2], &sC16[2 * ks][0], b0, b1);
            }
        }
    }

    __syncthreads();   // compute done; reuse smem

    // Row sums in lC col 0 (ll == 0: c0 = row lq, c2 = row lq+8)
    if (ll == 0) {
        lred[warp_n * 128 + m0w + lq]     = lC[0];
        lred[warp_n * 128 + m0w + 8 + lq] = lC[2];
    }
    if (warp_n == 1) {
        #pragma unroll
        for (int nt2 = 0; nt2 < 8; nt2++) {
            int row = m0w + lq;
            int col = nt2 * 8 + 2 * ll;
            *(float2*)(Opart + row * 68 + col) =
                make_float2(oC[nt2][0], oC[nt2][1]);
            *(float2*)(Opart + (row + 8) * 68 + col) =
                make_float2(oC[nt2][2], oC[nt2][3]);
        }
    }
    __syncthreads();

    if (warp_n == 0) {
        uint32_t* Og = g_O + (size_t)h * SS * 32;
        int row = m0w + lq;
        float li0 = 1.0f / (lred[row] + lred[128 + row]);
        float li1 = 1.0f / (lred[row + 8] + lred[128 + row + 8]);
        #pragma unroll
        for (int nt2 = 0; nt2 < 8; nt2++) {
            int col = nt2 * 8 + 2 * ll;
            float2 p0 = *(float2*)(Opart + row * 68 + col);
            float2 p1 = *(float2*)(Opart + (row + 8) * 68 + col);
            Og[(size_t)(m0 + row) * 32 + (col >> 1)] =
                pkh2((oC[nt2][0] + p0.x) * li0,
                     (oC[nt2][1] + p0.y) * li0);
            Og[(size_t)(m0 + row + 8) * 32 + (col >> 1)] =
                pkh2((oC[nt2][2] + p1.x) * li1,
                     (oC[nt2][3] + p1.y) * li1);
        }
    }
}

// ---------------------------------------------------------------------------
extern "C" void kernel_launch(void* const* d_in, const int* in_sizes, int n_in,
                              void* d_out, int out_size)
{
    const float* q  = (const float*)d_in[0];
    const float* k  = (const float*)d_in[1];
    const float* v  = (const float*)d_in[2];
    const float* Wq = (const float*)d_in[3];
    const float* bq = (const float*)d_in[4];
    const float* Wk = (const float*)d_in[5];
    const float* bk = (const float*)d_in[6];
    const float* Wv = (const float*)d_in[7];
    const float* bv = (const float*)d_in[8];
    const float* Wo = (const float*)d_in[9];
    const float* bo = (const float*)d_in[10];
    float* out = (float*)d_out;

    preconv<<<1024, 256>>>(q, k, v);
    transpose_w<<<dim3(32, 2, 64), dim3(32, 8)>>>(Wq, Wk, Wv, Wo);

    cudaFuncSetAttribute(proj_mma_kernel,
                         cudaFuncAttributeMaxDynamicSharedMemorySize, PROJ_SMEM);
    proj_mma_kernel<<<dim3(SS / 128, HH, 3), 256, PROJ_SMEM>>>(bq, bk, bv);

    cudaFuncSetAttribute(attn_kernel,
                         cudaFuncAttributeMaxDynamicSharedMemorySize, ATTN_SMEM);
    attn_kernel<<<dim3(SS / 128, HH), 512, ATTN_SMEM>>>();

    cudaFuncSetAttribute(outproj_mma_kernel,
                         cudaFuncAttributeMaxDynamicSharedMemorySize, PROJ_SMEM);
    outproj_mma_kernel<<<dim3(SS / 128, DD / 64), 256, PROJ_SMEM>>>(bo, out);
}

// round 17
// speedup vs baseline: 1.2235x; 1.2235x over previous
#include <cuda_runtime.h>
#include <cuda_fp16.h>
#include <cstdint>

#define SS 4096
#define DD 1024
#define HH 16
#define DHH 64
#define SCALE_L2E 0.045111762f             // (1/32) * log2(e)

// pack two f32 -> half2 (lo = first arg)
__device__ __forceinline__ uint32_t pkh2(float lo, float hi) {
    uint32_t r;
    asm("cvt.rn.f16x2.f32 %0, %1, %2;" : "=r"(r) : "f"(hi), "f"(lo));
    return r;
}
__device__ __forceinline__ uint32_t h2exp2(uint32_t x) {
    uint32_t r; asm("ex2.approx.f16x2 %0, %1;" : "=r"(r) : "r"(x)); return r;
}
__device__ __forceinline__ uint32_t hadd2(uint32_t a, uint32_t b) {
    uint32_t r; asm("add.f16x2 %0, %1, %2;" : "=r"(r) : "r"(a), "r"(b));
    return r;
}
__device__ __forceinline__ void mma_f16(float* d, const uint32_t* a,
                                        uint32_t b0, uint32_t b1) {
    asm volatile(
        "mma.sync.aligned.m16n8k16.row.col.f32.f16.f16.f32 "
        "{%0,%1,%2,%3}, {%4,%5,%6,%7}, {%8,%9}, {%0,%1,%2,%3};"
        : "+f"(d[0]), "+f"(d[1]), "+f"(d[2]), "+f"(d[3])
        : "r"(a[0]), "r"(a[1]), "r"(a[2]), "r"(a[3]), "r"(b0), "r"(b1));
}
// f16 accumulator variant (C/D = 2 regs of half2)
__device__ __forceinline__ void mma_f16c16(uint32_t* d, const uint32_t* a,
                                           uint32_t b0, uint32_t b1) {
    asm volatile(
        "mma.sync.aligned.m16n8k16.row.col.f16.f16.f16.f16 "
        "{%0,%1}, {%2,%3,%4,%5}, {%6,%7}, {%0,%1};"
        : "+r"(d[0]), "+r"(d[1])
        : "r"(a[0]), "r"(a[1]), "r"(a[2]), "r"(a[3]), "r"(b0), "r"(b1));
}
__device__ __forceinline__ uint32_t smem_to_u32(const void* p) {
    uint32_t a;
    asm("{ .reg .u64 t; cvta.to.shared.u64 t, %1; cvt.u32.u64 %0, t; }"
        : "=r"(a) : "l"(p));
    return a;
}
__device__ __forceinline__ void cp16(uint32_t dst, const void* src) {
    size_t g = __cvta_generic_to_global(src);
    asm volatile("cp.async.cg.shared.global [%0], [%1], 16;"
                 :: "r"(dst), "l"(g) : "memory");
}
#define CP_COMMIT() asm volatile("cp.async.commit_group;" ::: "memory")
#define CP_WAIT0()  asm volatile("cp.async.wait_group 0;" ::: "memory")

// Scratch (all fp16, stored as packed uint32 words = half2)
__device__ uint32_t g_X[3 * SS * DD / 2];     // q,k,v inputs [z][s][d]
__device__ uint32_t g_Q[HH * SS * DHH / 2];   // [h][s][e], pre-scaled by SCALE_L2E
__device__ uint32_t g_K[HH * SS * DHH / 2];   // [h][s][e]
__device__ uint32_t g_V[HH * SS * DHH / 2];   // [h][s/2][e][2] key-pair interleaved
__device__ uint32_t g_O[HH * SS * DHH / 2];   // [h][s][e]
__device__ uint32_t g_WT[64 * 64 * 1024 / 2]; // [slab][n][k] transposed weights

// ---------------------------------------------------------------------------
// Pre-convert q,k,v to fp16
// ---------------------------------------------------------------------------
__global__ __launch_bounds__(256) void preconv(
    const float* __restrict__ q, const float* __restrict__ k,
    const float* __restrict__ v)
{
    const int n4 = SS * DD / 4;
    for (int idx = blockIdx.x * 256 + threadIdx.x; idx < 3 * n4;
         idx += gridDim.x * 256) {
        int which = idx / n4, off = idx - which * n4;
        const float* src = (which == 0) ? q : (which == 1) ? k : v;
        float4 vv = *(const float4*)(src + (size_t)off * 4);
        uint2 u;
        u.x = pkh2(vv.x, vv.y);
        u.y = pkh2(vv.z, vv.w);
        *(uint2*)(g_X + (size_t)idx * 2) = u;
    }
}

// ---------------------------------------------------------------------------
// Weight pre-transpose: W[d][e] -> g_WT[slab][e][d] fp16
// ---------------------------------------------------------------------------
__global__ __launch_bounds__(256) void transpose_w(
    const float* __restrict__ Wq, const float* __restrict__ Wk,
    const float* __restrict__ Wv, const float* __restrict__ Wo)
{
    __shared__ float tile[32][33];
    const int slab = blockIdx.z, which = slab >> 4, hh = slab & 15;
    const float* src; int ld; size_t off;
    if (which == 0)      { src = Wq; ld = DHH; off = (size_t)hh * DD * DHH; }
    else if (which == 1) { src = Wk; ld = DHH; off = (size_t)hh * DD * DHH; }
    else if (which == 2) { src = Wv; ld = DHH; off = (size_t)hh * DD * DHH; }
    else                 { src = Wo; ld = DD;  off = (size_t)hh * 64; }
    const int d0 = blockIdx.x * 32, e0 = blockIdx.y * 32;
    const int tx = threadIdx.x, ty = threadIdx.y;
    #pragma unroll
    for (int j = 0; j < 32; j += 8)
        tile[ty + j][tx] = src[off + (size_t)(d0 + ty + j) * ld + e0 + tx];
    __syncthreads();
    __half* dst = (__half*)g_WT + (size_t)slab * 65536;
    #pragma unroll
    for (int j = 0; j < 32; j += 8)
        dst[(size_t)(e0 + ty + j) * 1024 + d0 + tx] =
            __float2half_rn(tile[tx][ty + j]);
}

// ---------------------------------------------------------------------------
// QKV projection, fp16 m16n8k16. CTA = (128 s-rows, head, which).
// ---------------------------------------------------------------------------
#define PROJ_SMEM ((128 * 36 + 64 * 36) * 4)

__global__ __launch_bounds__(256, 2) void proj_mma_kernel(
    const float* __restrict__ bq, const float* __restrict__ bk,
    const float* __restrict__ bv)
{
    extern __shared__ uint32_t sm[];
    uint32_t* As = sm;            // [128][36]
    uint32_t* Ws = sm + 128 * 36; // [64][36]

    const int z  = blockIdx.z;
    const int h  = blockIdx.y;
    const int m0 = blockIdx.x * 128;
    const uint32_t* A  = g_X + (size_t)z * SS * DD / 2;
    const float* biasp = ((z == 0) ? bq : (z == 1) ? bk : bv) + h * DHH;
    uint32_t* out = ((z == 0) ? g_Q : (z == 1) ? g_K : g_V)
                    + (size_t)h * SS * DHH / 2;
    const uint32_t* WT = g_WT + (size_t)(z * 16 + h) * 32768;

    const int t = threadIdx.x, wid = t >> 5, lane = t & 31;
    const int m0w = (wid >> 1) * 32, n0w = (wid & 1) * 32;
    const int lq = lane >> 2, ll = lane & 3;

    float c[2][4][4] = {};

    for (int kc = 0; kc < 16; kc++) {
        __syncthreads();
        #pragma unroll
        for (int it = 0; it < 4; it++) {
            int idx = t + it * 256;
            int r = idx >> 3, cc = (idx & 7) * 4;
            *(uint4*)(As + r * 36 + cc) =
                *(const uint4*)(A + (size_t)(m0 + r) * 512 + kc * 32 + cc);
        }
        #pragma unroll
        for (int it = 0; it < 2; it++) {
            int idx = t + it * 256;
            int e = idx >> 3, cc = (idx & 7) * 4;
            *(uint4*)(Ws + e * 36 + cc) =
                *(const uint4*)(WT + (size_t)e * 512 + kc * 32 + cc);
        }
        __syncthreads();

        #pragma unroll
        for (int ks = 0; ks < 4; ks++) {
            const int kb = ks * 8 + ll;
            uint32_t a[2][4];
            #pragma unroll
            for (int mt = 0; mt < 2; mt++) {
                int row = m0w + mt * 16 + lq;
                a[mt][0] = As[row * 36 + kb];
                a[mt][1] = As[(row + 8) * 36 + kb];
                a[mt][2] = As[row * 36 + kb + 4];
                a[mt][3] = As[(row + 8) * 36 + kb + 4];
            }
            #pragma unroll
            for (int nt = 0; nt < 4; nt++) {
                int n = n0w + nt * 8 + lq;
                uint32_t b0 = Ws[n * 36 + kb];
                uint32_t b1 = Ws[n * 36 + kb + 4];
                mma_f16(c[0][nt], a[0], b0, b1);
                mma_f16(c[1][nt], a[1], b0, b1);
            }
        }
    }

    if (z == 2) {
        __half* oh = (__half*)out;
        #pragma unroll
        for (int mt = 0; mt < 2; mt++) {
            #pragma unroll
            for (int nt = 0; nt < 4; nt++) {
                int col = n0w + nt * 8 + 2 * ll;
                float b0 = biasp[col], b1 = biasp[col + 1];
                #pragma unroll
                for (int rr = 0; rr < 2; rr++) {
                    int s = m0 + m0w + mt * 16 + lq + rr * 8;
                    size_t base = (size_t)(s >> 1) * 128 + (s & 1);
                    oh[base + col * 2] =
                        __float2half_rn(c[mt][nt][rr * 2 + 0] + b0);
                    oh[base + (col + 1) * 2] =
                        __float2half_rn(c[mt][nt][rr * 2 + 1] + b1);
                }
            }
        }
    } else {
        const float osc = (z == 0) ? SCALE_L2E : 1.0f;
        #pragma unroll
        for (int mt = 0; mt < 2; mt++) {
            #pragma unroll
            for (int nt = 0; nt < 4; nt++) {
                int col = n0w + nt * 8 + 2 * ll;
                float b0 = biasp[col], b1 = biasp[col + 1];
                #pragma unroll
                for (int rr = 0; rr < 2; rr++) {
                    int s = m0 + m0w + mt * 16 + lq + rr * 8;
                    out[(size_t)s * 32 + (col >> 1)] =
                        pkh2((c[mt][nt][rr * 2 + 0] + b0) * osc,
                             (c[mt][nt][rr * 2 + 1] + b1) * osc);
                }
            }
        }
    }
}

// ---------------------------------------------------------------------------
// Output projection, fp16. Chunk kc == head (gather from g_O). f32 output.
// ---------------------------------------------------------------------------
__global__ __launch_bounds__(256, 2) void outproj_mma_kernel(
    const float* __restrict__ bo, float* __restrict__ Cout)
{
    extern __shared__ uint32_t sm[];
    uint32_t* As = sm;
    uint32_t* Ws = sm + 128 * 36;

    const int m0 = blockIdx.x * 128;
    const int n0 = blockIdx.y * 64;
    const uint32_t* WT = g_WT + (size_t)(48 + blockIdx.y) * 32768;
    const float* biasp = bo + n0;

    const int t = threadIdx.x, wid = t >> 5, lane = t & 31;
    const int m0w = (wid >> 1) * 32, n0w = (wid & 1) * 32;
    const int lq = lane >> 2, ll = lane & 3;

    float c[2][4][4] = {};

    for (int kc = 0; kc < 16; kc++) {
        const uint32_t* A = g_O + (size_t)kc * SS * 32;
        __syncthreads();
        #pragma unroll
        for (int it = 0; it < 4; it++) {
            int idx = t + it * 256;
            int r = idx >> 3, cc = (idx & 7) * 4;
            *(uint4*)(As + r * 36 + cc) =
                *(const uint4*)(A + (size_t)(m0 + r) * 32 + cc);
        }
        #pragma unroll
        for (int it = 0; it < 2; it++) {
            int idx = t + it * 256;
            int e = idx >> 3, cc = (idx & 7) * 4;
            *(uint4*)(Ws + e * 36 + cc) =
                *(const uint4*)(WT + (size_t)e * 512 + kc * 32 + cc);
        }
        __syncthreads();

        #pragma unroll
        for (int ks = 0; ks < 4; ks++) {
            const int kb = ks * 8 + ll;
            uint32_t a[2][4];
            #pragma unroll
            for (int mt = 0; mt < 2; mt++) {
                int row = m0w + mt * 16 + lq;
                a[mt][0] = As[row * 36 + kb];
                a[mt][1] = As[(row + 8) * 36 + kb];
                a[mt][2] = As[row * 36 + kb + 4];
                a[mt][3] = As[(row + 8) * 36 + kb + 4];
            }
            #pragma unroll
            for (int nt = 0; nt < 4; nt++) {
                int n = n0w + nt * 8 + lq;
                uint32_t b0 = Ws[n * 36 + kb];
                uint32_t b1 = Ws[n * 36 + kb + 4];
                mma_f16(c[0][nt], a[0], b0, b1);
                mma_f16(c[1][nt], a[1], b0, b1);
            }
        }
    }

    #pragma unroll
    for (int mt = 0; mt < 2; mt++) {
        int row = m0w + mt * 16 + lq;
        #pragma unroll
        for (int nt = 0; nt < 4; nt++) {
            int col = n0w + nt * 8 + 2 * ll;
            float2 o0 = make_float2(c[mt][nt][0] + biasp[col],
                                    c[mt][nt][1] + biasp[col + 1]);
            float2 o1 = make_float2(c[mt][nt][2] + biasp[col],
                                    c[mt][nt][3] + biasp[col + 1]);
            *(float2*)(Cout + (size_t)(m0 + row) * DD + n0 + col) = o0;
            *(float2*)(Cout + (size_t)(m0 + row + 8) * DD + n0 + col) = o1;
        }
    }
}

// ---------------------------------------------------------------------------
// Flash attention, fp16 m16n8k16, 8 warps (4m x 2n; warp = 32 q x 64 keys)
// — the validated R12 shape. f16 S-accumulators; exp in place; frags feed
// PV directly. Row sums via HADD2 tree on the P fragments (fma/alu pipes,
// replaces the ones-column MMA: -8 HMMA/tile). 256-key chunks, cp.async
// double-buffered.
// smem (words): Qs[4608] | Ks0[256*36] | Ks1 | Vs0[128*72] | Vs1  = 41472
// Epilogue reuse: Opart @0 (128x68 f32), lred @8704 ([2][128]).
// ---------------------------------------------------------------------------
#define ATTN_SMEM (41472 * 4)

__global__ __launch_bounds__(256, 1) void attn_kernel()
{
    extern __shared__ uint32_t smu[];
    const uint32_t sb = smem_to_u32(smu);
    uint32_t* Qs = smu;                               // [128][36]
    uint32_t* Ksb[2] = { smu + 4608, smu + 13824 };   // each [256][36]
    uint32_t* Vsb[2] = { smu + 23040, smu + 32256 };  // each [128][72]
    const uint32_t ksw[2] = { sb + 4608 * 4, sb + 13824 * 4 };
    const uint32_t vsw[2] = { sb + 23040 * 4, sb + 32256 * 4 };
    float* Opart = (float*)smu;            // [128][68]
    float* lred  = (float*)(smu + 8704);   // [2][128]

    const int t      = threadIdx.x;
    const int wid    = t >> 5;
    const int lane   = t & 31;
    const int warp_n = wid & 1;
    const int m0w    = (wid >> 1) * 32;
    const int n0w    = warp_n * 64;
    const int lq     = lane >> 2;
    const int ll     = lane & 3;

    const int m0 = blockIdx.x * 128;
    const int h  = blockIdx.y;
    const uint32_t* Qg = g_Q + (size_t)h * SS * 32;
    const uint32_t* Kg = g_K + (size_t)h * SS * 32;
    const uint32_t* Vg = g_V + (size_t)h * SS * 32;

    auto issue_kv2 = [&](int kb0, int buf) {
        #pragma unroll
        for (int it = 0; it < 8; it++) {
            int idx = t + it * 256;
            int r = idx >> 3, cc = (idx & 7) * 4;
            cp16(ksw[buf] + (r * 36 + cc) * 4,
                 Kg + (size_t)(kb0 + r) * 32 + cc);
        }
        #pragma unroll
        for (int it = 0; it < 8; it++) {
            int idx = t + it * 256;
            int r = idx >> 4, cc = (idx & 15) * 4;
            cp16(vsw[buf] + (r * 72 + cc) * 4,
                 Vg + (size_t)((kb0 >> 1) + r) * 64 + cc);
        }
        CP_COMMIT();
    };

    // Q fill (grouped with chunk 0)
    #pragma unroll
    for (int it = 0; it < 4; it++) {
        int idx = t + it * 256;
        int r = idx >> 3, cc = (idx & 7) * 4;
        cp16(sb + (r * 36 + cc) * 4, Qg + (size_t)(m0 + r) * 32 + cc);
    }
    issue_kv2(0, 0);

    float oC[2][8][4];
    #pragma unroll
    for (int mt = 0; mt < 2; mt++)
        #pragma unroll
        for (int nt = 0; nt < 8; nt++)
            #pragma unroll
            for (int i = 0; i < 4; i++) oC[mt][nt][i] = 0.0f;
    float lacc[2][2] = {};
    uint32_t qa[2][4][4];   // hoisted Q fragments [mt][ks][frag]

    for (int ch = 0; ch < 16; ch++) {
        const int cur = ch & 1;
        CP_WAIT0();
        __syncthreads();
        if (ch == 0) {
            #pragma unroll
            for (int ks = 0; ks < 4; ks++) {
                const int kb = ks * 8 + ll;
                #pragma unroll
                for (int mt = 0; mt < 2; mt++) {
                    int row = m0w + mt * 16 + lq;
                    qa[mt][ks][0] = Qs[row * 36 + kb];
                    qa[mt][ks][1] = Qs[(row + 8) * 36 + kb];
                    qa[mt][ks][2] = Qs[row * 36 + kb + 4];
                    qa[mt][ks][3] = Qs[(row + 8) * 36 + kb + 4];
                }
            }
        }
        if (ch < 15) issue_kv2((ch + 1) * 256, cur ^ 1);

        #pragma unroll
        for (int hf = 0; hf < 2; hf++) {
            uint32_t* Ks = Ksb[cur] + hf * (128 * 36);
            uint32_t* Vs = Vsb[cur] + hf * (64 * 72);

            // S = Q K^T with f16 accumulators: sC16[mt][nt][2]
            uint32_t sC16[2][8][2];
            #pragma unroll
            for (int mt = 0; mt < 2; mt++)
                #pragma unroll
                for (int nt = 0; nt < 8; nt++) {
                    sC16[mt][nt][0] = 0u; sC16[mt][nt][1] = 0u;
                }
            #pragma unroll
            for (int ks = 0; ks < 4; ks++) {
                const int kb = ks * 8 + ll;
                #pragma unroll
                for (int nt = 0; nt < 8; nt++) {
                    int key = n0w + nt * 8 + lq;
                    uint32_t b0 = Ks[key * 36 + kb];
                    uint32_t b1 = Ks[key * 36 + kb + 4];
                    mma_f16c16(sC16[0][nt], qa[0][ks], b0, b1);
                    mma_f16c16(sC16[1][nt], qa[1][ks], b0, b1);
                }
            }

            // P = 2^S in place (scale folded into Q); frags become PV A-frags
            #pragma unroll
            for (int mt = 0; mt < 2; mt++)
                #pragma unroll
                for (int nt = 0; nt < 8; nt++) {
                    sC16[mt][nt][0] = h2exp2(sC16[mt][nt][0]);
                    sC16[mt][nt][1] = h2exp2(sC16[mt][nt][1]);
                }

            // Row sums via HADD2 tree (fma/alu pipes; replaces ones-MMA)
            #pragma unroll
            for (int mt = 0; mt < 2; mt++)
                #pragma unroll
                for (int half = 0; half < 2; half++) {
                    uint32_t s01 = hadd2(sC16[mt][0][half], sC16[mt][1][half]);
                    uint32_t s23 = hadd2(sC16[mt][2][half], sC16[mt][3][half]);
                    uint32_t s45 = hadd2(sC16[mt][4][half], sC16[mt][5][half]);
                    uint32_t s67 = hadd2(sC16[mt][6][half], sC16[mt][7][half]);
                    uint32_t sAll = hadd2(hadd2(s01, s23), hadd2(s45, s67));
                    float2 f = __half22float2(*(__half2*)&sAll);
                    lacc[mt][half] += f.x + f.y;
                }

            // O += P V. A = &sC16[mt][2ks][0] (4 contiguous regs)
            #pragma unroll
            for (int ks = 0; ks < 4; ks++) {
                int vbase = (n0w >> 1) + ks * 8;
                #pragma unroll
                for (int nt2 = 0; nt2 < 8; nt2++) {
                    int e = nt2 * 8 + lq;
                    uint32_t b0 = Vs[(vbase + ll) * 72 + e];
                    uint32_t b1 = Vs[(vbase + ll + 4) * 72 + e];
                    mma_f16(oC[0][nt2], &sC16[0][2 * ks][0], b0, b1);
                    mma_f16(oC[1][nt2], &sC16[1][2 * ks][0], b0, b1);
                }
            }
        }
    }

    __syncthreads();   // compute done; reuse smem

    // Quad-reduce row sums (lanes sharing lq differ in ll = bits 0-1)
    #pragma unroll
    for (int mt = 0; mt < 2; mt++)
        #pragma unroll
        for (int half = 0; half < 2; half++) {
            float ls = lacc[mt][half];
            ls += __shfl_xor_sync(0xffffffffu, ls, 1);
            ls += __shfl_xor_sync(0xffffffffu, ls, 2);
            if (ll == 0)
                lred[warp_n * 128 + m0w + mt * 16 + half * 8 + lq] = ls;
        }
    if (warp_n == 1) {
        #pragma unroll
        for (int mt = 0; mt < 2; mt++)
            #pragma unroll
            for (int nt2 = 0; nt2 < 8; nt2++) {
                int row = m0w + mt * 16 + lq;
                int col = nt2 * 8 + 2 * ll;
                *(float2*)(Opart + row * 68 + col) =
                    make_float2(oC[mt][nt2][0], oC[mt][nt2][1]);
                *(float2*)(Opart + (row + 8) * 68 + col) =
                    make_float2(oC[mt][nt2][2], oC[mt][nt2][3]);
            }
    }
    __syncthreads();

    if (warp_n == 0) {
        uint32_t* Og = g_O + (size_t)h * SS * 32;
        #pragma unroll
        for (int mt = 0; mt < 2; mt++) {
            int row = m0w + mt * 16 + lq;
            float li0 = 1.0f / (lred[row] + lred[128 + row]);
            float li1 = 1.0f / (lred[row + 8] + lred[128 + row + 8]);
            #pragma unroll
            for (int nt2 = 0; nt2 < 8; nt2++) {
                int col = nt2 * 8 + 2 * ll;
                float2 p0 = *(float2*)(Opart + row * 68 + col);
                float2 p1 = *(float2*)(Opart + (row + 8) * 68 + col);
                Og[(size_t)(m0 + row) * 32 + (col >> 1)] =
                    pkh2((oC[mt][nt2][0] + p0.x) * li0,
                         (oC[mt][nt2][1] + p0.y) * li0);
                Og[(size_t)(m0 + row + 8) * 32 + (col >> 1)] =
                    pkh2((oC[mt][nt2][2] + p1.x) * li1,
                         (oC[mt][nt2][3] + p1.y) * li1);
            }
        }
    }
}

// ---------------------------------------------------------------------------
extern "C" void kernel_launch(void* const* d_in, const int* in_sizes, int n_in,
                              void* d_out, int out_size)
{
    const float* q  = (const float*)d_in[0];
    const float* k  = (const float*)d_in[1];
    const float* v  = (const float*)d_in[2];
    const float* Wq = (const float*)d_in[3];
    const float* bq = (const float*)d_in[4];
    const float* Wk = (const float*)d_in[5];
    const float* bk = (const float*)d_in[6];
    const float* Wv = (const float*)d_in[7];
    const float* bv = (const float*)d_in[8];
    const float* Wo = (const float*)d_in[9];
    const float* bo = (const float*)d_in[10];
    float* out = (float*)d_out;

    preconv<<<1024, 256>>>(q, k, v);
    transpose_w<<<dim3(32, 2, 64), dim3(32, 8)>>>(Wq, Wk, Wv, Wo);

    cudaFuncSetAttribute(proj_mma_kernel,
                         cudaFuncAttributeMaxDynamicSharedMemorySize, PROJ_SMEM);
    proj_mma_kernel<<<dim3(SS / 128, HH, 3), 256, PROJ_SMEM>>>(bq, bk, bv);

    cudaFuncSetAttribute(attn_kernel,
                         cudaFuncAttributeMaxDynamicSharedMemorySize, ATTN_SMEM);
    attn_kernel<<<dim3(SS / 128, HH), 256, ATTN_SMEM>>>();

    cudaFuncSetAttribute(outproj_mma_kernel,
                         cudaFuncAttributeMaxDynamicSharedMemorySize, PROJ_SMEM);
    outproj_mma_kernel<<<dim3(SS / 128, DD / 64), 256, PROJ_SMEM>>>(bo, out);
}